// round 8
// baseline (speedup 1.0000x reference)
#include <cuda_runtime.h>
#include <cuda_bf16.h>
#include <cuda_fp8.h>
#include <mma.h>

using namespace nvcuda;

#define NN   50000
#define EE   800000
#define FIN  256
#define HH   8
#define CC   32
#define HC   256   // HH*CC
#define NOUT 40
#define NEG_SLOPE 0.2f
#define NB   ((NN + 255) / 256)

// ---------------- device scratch ----------------
__device__ unsigned char g_h[(size_t)NN * HC];   // 12.8 MB : projected features (fp8 e4m3)
__device__ float g_act1[(size_t)NN * CC];
__device__ float g_act2[(size_t)NN * CC];
__device__ float g_asrc[NN * HH];
__device__ float g_adst[NN * HH];
__device__ int   g_deg[NN];
__device__ int   g_rowptr[NN + 1];
__device__ int   g_cursor[NN];
__device__ int   g_csr[EE];
__device__ int   g_bsum[NB];
__device__ int   g_boff[NB];

// fp8x2 -> float2 helper
__device__ __forceinline__ float2 fp8x2_to_float2(unsigned short v) {
    __half2_raw hr = __nv_cvt_fp8x2_to_halfraw2((__nv_fp8x2_storage_t)v, __NV_E4M3);
    return __half22float2(*(__half2*)&hr);
}

// ---------------- CSR build ----------------
__global__ void zero_kernel() {
    int i = blockIdx.x * blockDim.x + threadIdx.x;
    if (i < NN) g_deg[i] = 0;
}

__global__ void count_kernel(const int* __restrict__ ei) {
    int e = blockIdx.x * blockDim.x + threadIdx.x;
    if (e < EE) atomicAdd(&g_deg[ei[EE + e]], 1);
}

__global__ void degsum_kernel() {
    __shared__ int sm[256];
    int i = blockIdx.x * 256 + threadIdx.x;
    int v = (i < NN) ? g_deg[i] : 0;
    sm[threadIdx.x] = v;
    __syncthreads();
    for (int o = 128; o > 0; o >>= 1) {
        if (threadIdx.x < o) sm[threadIdx.x] += sm[threadIdx.x + o];
        __syncthreads();
    }
    if (threadIdx.x == 0) g_bsum[blockIdx.x] = sm[0];
}

__global__ void scanb_kernel() {
    __shared__ int sm[256];
    int t = threadIdx.x;
    int v = (t < NB) ? g_bsum[t] : 0;
    sm[t] = v;
    __syncthreads();
    for (int o = 1; o < 256; o <<= 1) {
        int u = (t >= o) ? sm[t - o] : 0;
        __syncthreads();
        sm[t] += u;
        __syncthreads();
    }
    if (t < NB) g_boff[t] = sm[t] - v;
}

__global__ void scanc_kernel() {
    __shared__ int sm[256];
    int b = blockIdx.x, t = threadIdx.x;
    int i = b * 256 + t;
    int v = (i < NN) ? g_deg[i] : 0;
    sm[t] = v;
    __syncthreads();
    for (int o = 1; o < 256; o <<= 1) {
        int u = (t >= o) ? sm[t - o] : 0;
        __syncthreads();
        sm[t] += u;
        __syncthreads();
    }
    int excl = g_boff[b] + sm[t] - v;
    if (i < NN) { g_rowptr[i] = excl; g_cursor[i] = 0; }
    if (i == NN - 1) g_rowptr[NN] = excl + v;
}

__global__ void fill_kernel(const int* __restrict__ ei) {
    int e = blockIdx.x * blockDim.x + threadIdx.x;
    if (e < EE) {
        int src = ei[e];
        int dst = ei[EE + e];
        int pos = atomicAdd(&g_cursor[dst], 1);
        g_csr[g_rowptr[dst] + pos] = src;
    }
}

// ---------------- bf16 tensor-core GEMM, fp8 output ----------------
#define GBM 128
#define GBN 128
#define GBK 32
__global__ __launch_bounds__(256) void gemm_bf16(const float* __restrict__ A,
                                                 const float* __restrict__ B,
                                                 unsigned char* __restrict__ Cmat,
                                                 int M, int Nc, int K) {
    __shared__ __nv_bfloat16 As[GBM][GBK + 8];
    __shared__ __nv_bfloat16 Bs[GBK][GBN + 8];
    __shared__ float stage[8][16 * 20];

    int tid = threadIdx.x;
    int wid = tid >> 5;
    int lane = tid & 31;
    int wm = wid >> 1;
    int wn = wid & 1;
    int bm = blockIdx.y * GBM;
    int bn = blockIdx.x * GBN;

    wmma::fragment<wmma::accumulator, 16, 16, 16, float> acc[2][4];
#pragma unroll
    for (int i = 0; i < 2; i++)
#pragma unroll
        for (int j = 0; j < 4; j++)
            wmma::fill_fragment(acc[i][j], 0.0f);

    int arow = tid >> 1;
    int acol = (tid & 1) * 16;
    int brow = tid >> 3;
    int bcol = (tid & 7) * 16;

    for (int k0 = 0; k0 < K; k0 += GBK) {
        {
            float4 v[4];
            if (bm + arow < M) {
                const float4* ap = (const float4*)(A + (size_t)(bm + arow) * K + k0 + acol);
#pragma unroll
                for (int t = 0; t < 4; t++) v[t] = ap[t];
            } else {
#pragma unroll
                for (int t = 0; t < 4; t++) v[t] = make_float4(0.f, 0.f, 0.f, 0.f);
            }
            __nv_bfloat16* dstp = &As[arow][acol];
#pragma unroll
            for (int t = 0; t < 4; t++) {
                dstp[4 * t + 0] = __float2bfloat16_rn(v[t].x);
                dstp[4 * t + 1] = __float2bfloat16_rn(v[t].y);
                dstp[4 * t + 2] = __float2bfloat16_rn(v[t].z);
                dstp[4 * t + 3] = __float2bfloat16_rn(v[t].w);
            }
        }
        {
            const float4* bp = (const float4*)(B + (size_t)(k0 + brow) * Nc + bn + bcol);
            __nv_bfloat16* dstp = &Bs[brow][bcol];
#pragma unroll
            for (int t = 0; t < 4; t++) {
                float4 v = bp[t];
                dstp[4 * t + 0] = __float2bfloat16_rn(v.x);
                dstp[4 * t + 1] = __float2bfloat16_rn(v.y);
                dstp[4 * t + 2] = __float2bfloat16_rn(v.z);
                dstp[4 * t + 3] = __float2bfloat16_rn(v.w);
            }
        }
        __syncthreads();
#pragma unroll
        for (int ks = 0; ks < GBK; ks += 16) {
            wmma::fragment<wmma::matrix_a, 16, 16, 16, __nv_bfloat16, wmma::row_major> af[2];
#pragma unroll
            for (int i = 0; i < 2; i++)
                wmma::load_matrix_sync(af[i], &As[wm * 32 + i * 16][ks], GBK + 8);
            wmma::fragment<wmma::matrix_b, 16, 16, 16, __nv_bfloat16, wmma::row_major> bf[4];
#pragma unroll
            for (int j = 0; j < 4; j++)
                wmma::load_matrix_sync(bf[j], &Bs[ks][wn * 64 + j * 16], GBN + 8);
#pragma unroll
            for (int i = 0; i < 2; i++)
#pragma unroll
                for (int j = 0; j < 4; j++)
                    wmma::mma_sync(acc[i][j], af[i], bf[j], acc[i][j]);
        }
        __syncthreads();
    }

    float* st = &stage[wid][0];
    int lr = lane >> 1;
    int lc = (lane & 1) * 8;
#pragma unroll
    for (int i = 0; i < 2; i++) {
#pragma unroll
        for (int j = 0; j < 4; j++) {
            wmma::store_matrix_sync(st, acc[i][j], 20, wmma::mem_row_major);
            __syncwarp();
            int row = bm + wm * 32 + i * 16 + lr;
            int col = bn + wn * 64 + j * 16 + lc;
            if (row < M) {
                unsigned char tmp[8];
#pragma unroll
                for (int t = 0; t < 8; t++)
                    tmp[t] = __nv_cvt_float_to_fp8(st[lr * 20 + lc + t], __NV_SATFINITE, __NV_E4M3);
                *(uint2*)(Cmat + (size_t)row * Nc + col) = *(uint2*)tmp;
            }
            __syncwarp();
        }
    }
}

// ---------------- attention coefficients (fp8 h) ----------------
__global__ void alpha_kernel(const unsigned char* __restrict__ hbuf,
                             const float* __restrict__ a_src,
                             const float* __restrict__ a_dst) {
    int idx = blockIdx.x * blockDim.x + threadIdx.x;
    if (idx >= NN * HH) return;
    int hd = idx & (HH - 1);
    uint4 raw0 = *(const uint4*)(hbuf + (size_t)idx * CC);
    uint4 raw1 = *(const uint4*)(hbuf + (size_t)idx * CC + 16);
    const unsigned short* p0 = (const unsigned short*)&raw0;
    const unsigned short* p1 = (const unsigned short*)&raw1;
    const float* as = a_src + hd * CC;
    const float* ad = a_dst + hd * CC;
    float s1 = 0.f, s2 = 0.f;
#pragma unroll
    for (int i = 0; i < 8; i++) {
        float2 v = fp8x2_to_float2(p0[i]);
        s1 += v.x * as[2 * i] + v.y * as[2 * i + 1];
        s2 += v.x * ad[2 * i] + v.y * ad[2 * i + 1];
    }
#pragma unroll
    for (int i = 0; i < 8; i++) {
        float2 v = fp8x2_to_float2(p1[i]);
        s1 += v.x * as[16 + 2 * i] + v.y * as[16 + 2 * i + 1];
        s2 += v.x * ad[16 + 2 * i] + v.y * ad[16 + 2 * i + 1];
    }
    g_asrc[idx] = s1;
    g_adst[idx] = s2;
}

__device__ __forceinline__ float lrelu(float e) { return e > 0.f ? e : NEG_SLOPE * e; }

// fp8x8 (uint2) -> accumulate 8 channels
__device__ __forceinline__ void accum8(float* acc, float ex, const uint2& raw) {
    const unsigned short* p = (const unsigned short*)&raw;
#pragma unroll
    for (int t = 0; t < 4; t++) {
        float2 v = fp8x2_to_float2(p[t]);
        acc[2 * t]     += ex * v.x;
        acc[2 * t + 1] += ex * v.y;
    }
}

// ---------------- gather aggregation: 2 warps per dst node ----------------
// Warp pair splits the edge list (stride 2); partials combined via smem.
// Block = 256 threads = 8 warps = 4 nodes. NN % 4 == 0, so no divergent syncthreads.
__global__ __launch_bounds__(256) void aggregate_kernel(const unsigned char* __restrict__ hbuf,
                                                        const float* __restrict__ asrc,
                                                        const float* __restrict__ adst,
                                                        const float* __restrict__ bias,
                                                        float* __restrict__ outbuf) {
    __shared__ float s_part[4][32][9];   // odd warp's acc[8] + s, per node-pair

    int tid = threadIdx.x;
    int wid = tid >> 5;
    int lane = tid & 31;
    int pair = wid >> 1;     // node slot within block: 0..3
    int half = wid & 1;      // which half of the edge list
    int dst = blockIdx.x * 4 + pair;

    int beg = g_rowptr[dst], end = g_rowptr[dst + 1];
    int hd = lane >> 2;           // head 0..7
    int cb = (lane & 3) * 8;      // channel base within head
    float adst_h = adst[dst * HH + hd];

    float s = 0.f;
    float acc[8] = {0.f, 0.f, 0.f, 0.f, 0.f, 0.f, 0.f, 0.f};

    // self-loop handled by half 0
    if (half == 0) {
        float ex_self = __expf(lrelu(asrc[dst * HH + hd] + adst_h));
        s = ex_self;
        uint2 raw = *(const uint2*)(hbuf + (size_t)dst * HC + hd * CC + cb);
        accum8(acc, ex_self, raw);
    }

    // stride-2 edge stream with depth-1 pipeline
    int i0 = beg + half;
    if (i0 < end) {
        int src0 = g_csr[i0];
        float a0 = asrc[src0 * HH + hd];
        uint2 r0 = *(const uint2*)(hbuf + (size_t)src0 * HC + hd * CC + cb);
        for (int i = i0 + 2; i < end; i += 2) {
            int src1 = g_csr[i];
            float a1 = asrc[src1 * HH + hd];
            uint2 r1 = *(const uint2*)(hbuf + (size_t)src1 * HC + hd * CC + cb);
            float ex = __expf(lrelu(a0 + adst_h));
            s += ex;
            accum8(acc, ex, r0);
            a0 = a1; r0 = r1;
        }
        float ex = __expf(lrelu(a0 + adst_h));
        s += ex;
        accum8(acc, ex, r0);
    }

    // combine: odd half publishes, even half reduces and finishes
    if (half == 1) {
#pragma unroll
        for (int j = 0; j < 8; j++) s_part[pair][lane][j] = acc[j];
        s_part[pair][lane][8] = s;
    }
    __syncthreads();
    if (half == 1) return;

#pragma unroll
    for (int j = 0; j < 8; j++) acc[j] += s_part[pair][lane][j];
    s += s_part[pair][lane][8];

    float inv = 1.f / s;
#pragma unroll
    for (int j = 0; j < 8; j++) acc[j] *= inv;

    // mean over heads: reduce across lanes differing in head bits
#pragma unroll
    for (int j = 0; j < 8; j++) {
        float v = acc[j];
        v += __shfl_xor_sync(0xffffffffu, v, 4);
        v += __shfl_xor_sync(0xffffffffu, v, 8);
        v += __shfl_xor_sync(0xffffffffu, v, 16);
        acc[j] = v * 0.125f;
    }

    if (lane < 4) {
        float o[8];
#pragma unroll
        for (int j = 0; j < 8; j++) {
            float v = acc[j] + bias[cb + j];
            o[j] = v > 0.f ? v : (__expf(v) - 1.f);
        }
        float4* op = (float4*)(outbuf + (size_t)dst * CC + cb);
        op[0] = make_float4(o[0], o[1], o[2], o[3]);
        op[1] = make_float4(o[4], o[5], o[6], o[7]);
    }
}

// ---------------- final projection (32->40) + log_softmax ----------------
__global__ __launch_bounds__(128) void final_kernel(const float* __restrict__ act,
                                                    const float* __restrict__ Wo,
                                                    const float* __restrict__ bo,
                                                    float* __restrict__ out) {
    __shared__ float sW[CC * NOUT];
    __shared__ float sb[NOUT];
    for (int i = threadIdx.x; i < CC * NOUT; i += blockDim.x) sW[i] = Wo[i];
    for (int i = threadIdx.x; i < NOUT; i += blockDim.x) sb[i] = bo[i];
    __syncthreads();
    int n = blockIdx.x * blockDim.x + threadIdx.x;
    if (n >= NN) return;
    float xr[CC];
    const float4* ap = (const float4*)(act + (size_t)n * CC);
#pragma unroll
    for (int i = 0; i < 8; i++) {
        float4 v = ap[i];
        xr[4 * i + 0] = v.x; xr[4 * i + 1] = v.y; xr[4 * i + 2] = v.z; xr[4 * i + 3] = v.w;
    }
    float lg[NOUT];
#pragma unroll
    for (int j = 0; j < NOUT; j++) {
        float sum = sb[j];
#pragma unroll
        for (int c = 0; c < CC; c++) sum += xr[c] * sW[c * NOUT + j];
        lg[j] = sum;
    }
    float m = lg[0];
#pragma unroll
    for (int j = 1; j < NOUT; j++) m = fmaxf(m, lg[j]);
    float se = 0.f;
#pragma unroll
    for (int j = 0; j < NOUT; j++) se += __expf(lg[j] - m);
    float lse = m + __logf(se);
    float* op = out + (size_t)n * NOUT;
#pragma unroll
    for (int j = 0; j < NOUT; j++) op[j] = lg[j] - lse;
}

// ---------------- launch ----------------
extern "C" void kernel_launch(void* const* d_in, const int* in_sizes, int n_in,
                              void* d_out, int out_size) {
    const float* x   = (const float*)d_in[0];
    const int*   ei  = (const int*)d_in[1];
    const float* W1  = (const float*)d_in[2];
    const float* as1 = (const float*)d_in[3];
    const float* ad1 = (const float*)d_in[4];
    const float* b1  = (const float*)d_in[5];
    const float* W2  = (const float*)d_in[6];
    const float* as2 = (const float*)d_in[7];
    const float* ad2 = (const float*)d_in[8];
    const float* b2  = (const float*)d_in[9];
    const float* Wo  = (const float*)d_in[10];
    const float* bo  = (const float*)d_in[11];
    float* out = (float*)d_out;

    unsigned char* hbuf;
    float *act1, *act2, *pasrc, *padst;
    cudaGetSymbolAddress((void**)&hbuf, g_h);
    cudaGetSymbolAddress((void**)&act1, g_act1);
    cudaGetSymbolAddress((void**)&act2, g_act2);
    cudaGetSymbolAddress((void**)&pasrc, g_asrc);
    cudaGetSymbolAddress((void**)&padst, g_adst);

    // one-time host resources for the parallel graph branch (no device memory)
    static cudaStream_t s_side = nullptr;
    static cudaEvent_t e_fork = nullptr, e_join = nullptr;
    if (s_side == nullptr) {
        cudaStreamCreateWithFlags(&s_side, cudaStreamNonBlocking);
        cudaEventCreateWithFlags(&e_fork, cudaEventDisableTiming);
        cudaEventCreateWithFlags(&e_join, cudaEventDisableTiming);
    }

    // ---- fork: GEMM1 + alpha1 parallel to CSR build ----
    cudaEventRecord(e_fork, 0);
    cudaStreamWaitEvent(s_side, e_fork, 0);

    dim3 gg(HC / GBN, (NN + GBM - 1) / GBM);
    gemm_bf16<<<gg, 256, 0, s_side>>>(x, W1, hbuf, NN, HC, FIN);
    alpha_kernel<<<(NN * HH + 255) / 256, 256, 0, s_side>>>(hbuf, as1, ad1);
    cudaEventRecord(e_join, s_side);

    // ---- CSR build on the main stream ----
    zero_kernel<<<NB, 256>>>();
    count_kernel<<<(EE + 255) / 256, 256>>>(ei);
    degsum_kernel<<<NB, 256>>>();
    scanb_kernel<<<1, 256>>>();
    scanc_kernel<<<NB, 256>>>();
    fill_kernel<<<(EE + 255) / 256, 256>>>(ei);

    // ---- join: aggregate1 needs both branches ----
    cudaStreamWaitEvent(0, e_join, 0);
    aggregate_kernel<<<NN / 4, 256>>>(hbuf, pasrc, padst, b1, act1);

    // ---- layer 2 ----
    gemm_bf16<<<gg, 256>>>(act1, W2, hbuf, NN, HC, CC);
    alpha_kernel<<<(NN * HH + 255) / 256, 256>>>(hbuf, as2, ad2);
    aggregate_kernel<<<NN / 4, 256>>>(hbuf, pasrc, padst, b2, act2);

    // ---- output head ----
    final_kernel<<<(NN + 127) / 128, 128>>>(act2, Wo, bo, out);
}

// round 9
// speedup vs baseline: 1.2987x; 1.2987x over previous
#include <cuda_runtime.h>
#include <cuda_bf16.h>
#include <cuda_fp8.h>
#include <mma.h>

using namespace nvcuda;

#define NN   50000
#define EE   800000
#define FIN  256
#define HH   8
#define CC   32
#define HC   256   // HH*CC
#define NOUT 40
#define NEG_SLOPE 0.2f
#define NB   ((NN + 255) / 256)

// ---------------- device scratch ----------------
__device__ unsigned char g_h[(size_t)NN * HC];   // 12.8 MB : projected features (fp8 e4m3)
__device__ float g_act1[(size_t)NN * CC];
__device__ float g_asrc[NN * HH];
__device__ float g_adst[NN * HH];
__device__ int   g_deg[NN];
__device__ int   g_rowptr[NN + 1];
__device__ int   g_cursor[NN];
__device__ int   g_csr[EE];
__device__ int   g_bsum[NB];
__device__ int   g_boff[NB];

// fp8x2 -> float2 helper
__device__ __forceinline__ float2 fp8x2_to_float2(unsigned short v) {
    __half2_raw hr = __nv_cvt_fp8x2_to_halfraw2((__nv_fp8x2_storage_t)v, __NV_E4M3);
    return __half22float2(*(__half2*)&hr);
}

// ---------------- CSR build ----------------
__global__ void zero_kernel() {
    int i = blockIdx.x * blockDim.x + threadIdx.x;
    if (i < NN) g_deg[i] = 0;
}

__global__ void count_kernel(const int* __restrict__ ei) {
    int e = blockIdx.x * blockDim.x + threadIdx.x;
    if (e < EE) atomicAdd(&g_deg[ei[EE + e]], 1);
}

__global__ void degsum_kernel() {
    __shared__ int sm[256];
    int i = blockIdx.x * 256 + threadIdx.x;
    int v = (i < NN) ? g_deg[i] : 0;
    sm[threadIdx.x] = v;
    __syncthreads();
    for (int o = 128; o > 0; o >>= 1) {
        if (threadIdx.x < o) sm[threadIdx.x] += sm[threadIdx.x + o];
        __syncthreads();
    }
    if (threadIdx.x == 0) g_bsum[blockIdx.x] = sm[0];
}

__global__ void scanb_kernel() {
    __shared__ int sm[256];
    int t = threadIdx.x;
    int v = (t < NB) ? g_bsum[t] : 0;
    sm[t] = v;
    __syncthreads();
    for (int o = 1; o < 256; o <<= 1) {
        int u = (t >= o) ? sm[t - o] : 0;
        __syncthreads();
        sm[t] += u;
        __syncthreads();
    }
    if (t < NB) g_boff[t] = sm[t] - v;
}

__global__ void scanc_kernel() {
    __shared__ int sm[256];
    int b = blockIdx.x, t = threadIdx.x;
    int i = b * 256 + t;
    int v = (i < NN) ? g_deg[i] : 0;
    sm[t] = v;
    __syncthreads();
    for (int o = 1; o < 256; o <<= 1) {
        int u = (t >= o) ? sm[t - o] : 0;
        __syncthreads();
        sm[t] += u;
        __syncthreads();
    }
    int excl = g_boff[b] + sm[t] - v;
    if (i < NN) { g_rowptr[i] = excl; g_cursor[i] = 0; }
    if (i == NN - 1) g_rowptr[NN] = excl + v;
}

__global__ void fill_kernel(const int* __restrict__ ei) {
    int e = blockIdx.x * blockDim.x + threadIdx.x;
    if (e < EE) {
        int src = ei[e];
        int dst = ei[EE + e];
        int pos = atomicAdd(&g_cursor[dst], 1);
        g_csr[g_rowptr[dst] + pos] = src;
    }
}

// ---------------- bf16 tensor-core GEMM, fp8 output, fused alpha epilogue ----------------
// Each warp's epilogue tiles cover 2 complete heads x 32 rows -> alpha dot products
// complete locally (pair-lane shfl), written straight to g_asrc/g_adst.
#define GBM 128
#define GBN 128
#define GBK 32
__global__ __launch_bounds__(256) void gemm_bf16(const float* __restrict__ A,
                                                 const float* __restrict__ B,
                                                 unsigned char* __restrict__ Cmat,
                                                 const float* __restrict__ a_src,
                                                 const float* __restrict__ a_dst,
                                                 int M, int Nc, int K) {
    __shared__ __nv_bfloat16 As[GBM][GBK + 8];
    __shared__ __nv_bfloat16 Bs[GBK][GBN + 8];
    __shared__ float stage[8][16 * 20];

    int tid = threadIdx.x;
    int wid = tid >> 5;
    int lane = tid & 31;
    int wm = wid >> 1;
    int wn = wid & 1;
    int bm = blockIdx.y * GBM;
    int bn = blockIdx.x * GBN;

    wmma::fragment<wmma::accumulator, 16, 16, 16, float> acc[2][4];
#pragma unroll
    for (int i = 0; i < 2; i++)
#pragma unroll
        for (int j = 0; j < 4; j++)
            wmma::fill_fragment(acc[i][j], 0.0f);

    int arow = tid >> 1;
    int acol = (tid & 1) * 16;
    int brow = tid >> 3;
    int bcol = (tid & 7) * 16;

    for (int k0 = 0; k0 < K; k0 += GBK) {
        {
            float4 v[4];
            if (bm + arow < M) {
                const float4* ap = (const float4*)(A + (size_t)(bm + arow) * K + k0 + acol);
#pragma unroll
                for (int t = 0; t < 4; t++) v[t] = ap[t];
            } else {
#pragma unroll
                for (int t = 0; t < 4; t++) v[t] = make_float4(0.f, 0.f, 0.f, 0.f);
            }
            __nv_bfloat16* dstp = &As[arow][acol];
#pragma unroll
            for (int t = 0; t < 4; t++) {
                dstp[4 * t + 0] = __float2bfloat16_rn(v[t].x);
                dstp[4 * t + 1] = __float2bfloat16_rn(v[t].y);
                dstp[4 * t + 2] = __float2bfloat16_rn(v[t].z);
                dstp[4 * t + 3] = __float2bfloat16_rn(v[t].w);
            }
        }
        {
            const float4* bp = (const float4*)(B + (size_t)(k0 + brow) * Nc + bn + bcol);
            __nv_bfloat16* dstp = &Bs[brow][bcol];
#pragma unroll
            for (int t = 0; t < 4; t++) {
                float4 v = bp[t];
                dstp[4 * t + 0] = __float2bfloat16_rn(v.x);
                dstp[4 * t + 1] = __float2bfloat16_rn(v.y);
                dstp[4 * t + 2] = __float2bfloat16_rn(v.z);
                dstp[4 * t + 3] = __float2bfloat16_rn(v.w);
            }
        }
        __syncthreads();
#pragma unroll
        for (int ks = 0; ks < GBK; ks += 16) {
            wmma::fragment<wmma::matrix_a, 16, 16, 16, __nv_bfloat16, wmma::row_major> af[2];
#pragma unroll
            for (int i = 0; i < 2; i++)
                wmma::load_matrix_sync(af[i], &As[wm * 32 + i * 16][ks], GBK + 8);
            wmma::fragment<wmma::matrix_b, 16, 16, 16, __nv_bfloat16, wmma::row_major> bf[4];
#pragma unroll
            for (int j = 0; j < 4; j++)
                wmma::load_matrix_sync(bf[j], &Bs[ks][wn * 64 + j * 16], GBN + 8);
#pragma unroll
            for (int i = 0; i < 2; i++)
#pragma unroll
                for (int j = 0; j < 4; j++)
                    wmma::mma_sync(acc[i][j], af[i], bf[j], acc[i][j]);
        }
        __syncthreads();
    }

    float* st = &stage[wid][0];
    int lr = lane >> 1;
    int lc = (lane & 1) * 8;
    int hb = (bn >> 5) + wn * 2;   // base head index for this warp (2 heads)
#pragma unroll
    for (int i = 0; i < 2; i++) {
        float al_s[2] = {0.f, 0.f};
        float al_d[2] = {0.f, 0.f};
        int row = bm + wm * 32 + i * 16 + lr;
#pragma unroll
        for (int j = 0; j < 4; j++) {
            wmma::store_matrix_sync(st, acc[i][j], 20, wmma::mem_row_major);
            __syncwarp();
            if (row < M) {
                int h = j >> 1;
                int colbase = (j & 1) * 16 + lc;   // column within head (0..31)
                const float* asp = a_src + (hb + h) * CC + colbase;
                const float* adp = a_dst + (hb + h) * CC + colbase;
                unsigned char tmp[8];
#pragma unroll
                for (int t = 0; t < 8; t++) {
                    float v = st[lr * 20 + lc + t];
                    tmp[t] = __nv_cvt_float_to_fp8(v, __NV_SATFINITE, __NV_E4M3);
                    al_s[h] += v * __ldg(asp + t);
                    al_d[h] += v * __ldg(adp + t);
                }
                int col = bn + wn * 64 + j * 16 + lc;
                *(uint2*)(Cmat + (size_t)row * Nc + col) = *(uint2*)tmp;
            }
            __syncwarp();
        }
        // combine lane pairs (same row, halves of the 16 cols) and write alpha
#pragma unroll
        for (int h = 0; h < 2; h++) {
            float vs = al_s[h] + __shfl_xor_sync(0xffffffffu, al_s[h], 1);
            float vd = al_d[h] + __shfl_xor_sync(0xffffffffu, al_d[h], 1);
            if (row < M && (lane & 1) == 0) {
                g_asrc[row * HH + hb + h] = vs;
                g_adst[row * HH + hb + h] = vd;
            }
        }
    }
}

__device__ __forceinline__ float lrelu(float e) { return e > 0.f ? e : NEG_SLOPE * e; }

// fp8x8 (uint2) -> accumulate 8 channels
__device__ __forceinline__ void accum8(float* acc, float ex, const uint2& raw) {
    const unsigned short* p = (const unsigned short*)&raw;
#pragma unroll
    for (int t = 0; t < 4; t++) {
        float2 v = fp8x2_to_float2(p[t]);
        acc[2 * t]     += ex * v.x;
        acc[2 * t + 1] += ex * v.y;
    }
}

// ---------------- single-pass gather aggregation (round-7 loop) ----------------
// Tail is dual-mode: layer-1 writes act (ELU+bias); layer-2 (fout != nullptr)
// fuses the 32->40 projection + log_softmax and writes d_out directly.
__global__ __launch_bounds__(256) void aggregate_kernel(const unsigned char* __restrict__ hbuf,
                                                        const float* __restrict__ asrc,
                                                        const float* __restrict__ adst,
                                                        const float* __restrict__ bias,
                                                        float* __restrict__ outbuf,
                                                        const float* __restrict__ Wo,
                                                        const float* __restrict__ bo,
                                                        float* __restrict__ fout) {
    __shared__ float sx[8][32];   // per-warp staged activation for fused final

    int w = (blockIdx.x * blockDim.x + threadIdx.x) >> 5;
    int wib = threadIdx.x >> 5;
    int lane = threadIdx.x & 31;
    if (w >= NN) return;
    int dst = w;
    int beg = g_rowptr[dst], end = g_rowptr[dst + 1];
    int hd = lane >> 2;           // head 0..7
    int cb = (lane & 3) * 8;      // channel base within head
    float adst_h = adst[dst * HH + hd];

    float ex_self = __expf(lrelu(asrc[dst * HH + hd] + adst_h));
    float s = ex_self;
    float acc[8] = {0.f, 0.f, 0.f, 0.f, 0.f, 0.f, 0.f, 0.f};
    {
        uint2 raw = *(const uint2*)(hbuf + (size_t)dst * HC + hd * CC + cb);
        accum8(acc, ex_self, raw);
    }

    if (beg < end) {
        int src0 = g_csr[beg];
        float a0 = asrc[src0 * HH + hd];
        uint2 r0 = *(const uint2*)(hbuf + (size_t)src0 * HC + hd * CC + cb);
        for (int i = beg + 1; i < end; ++i) {
            int src1 = g_csr[i];
            float a1 = asrc[src1 * HH + hd];
            uint2 r1 = *(const uint2*)(hbuf + (size_t)src1 * HC + hd * CC + cb);
            float ex = __expf(lrelu(a0 + adst_h));
            s += ex;
            accum8(acc, ex, r0);
            a0 = a1; r0 = r1;
        }
        float ex = __expf(lrelu(a0 + adst_h));
        s += ex;
        accum8(acc, ex, r0);
    }

    float inv = 1.f / s;
#pragma unroll
    for (int j = 0; j < 8; j++) acc[j] *= inv;

    // mean over heads
#pragma unroll
    for (int j = 0; j < 8; j++) {
        float v = acc[j];
        v += __shfl_xor_sync(0xffffffffu, v, 4);
        v += __shfl_xor_sync(0xffffffffu, v, 8);
        v += __shfl_xor_sync(0xffffffffu, v, 16);
        acc[j] = v * 0.125f;
    }

    if (fout == nullptr) {
        // layer-1 tail: bias + ELU -> act buffer
        if (lane < 4) {
            float o[8];
#pragma unroll
            for (int j = 0; j < 8; j++) {
                float v = acc[j] + bias[cb + j];
                o[j] = v > 0.f ? v : (__expf(v) - 1.f);
            }
            float4* op = (float4*)(outbuf + (size_t)dst * CC + cb);
            op[0] = make_float4(o[0], o[1], o[2], o[3]);
            op[1] = make_float4(o[4], o[5], o[6], o[7]);
        }
    } else {
        // layer-2 tail: bias + ELU -> smem, then fused 32->40 proj + log_softmax
        if (lane < 4) {
#pragma unroll
            for (int j = 0; j < 8; j++) {
                float v = acc[j] + bias[cb + j];
                sx[wib][cb + j] = v > 0.f ? v : (__expf(v) - 1.f);
            }
        }
        __syncwarp();
        const float* xv = sx[wib];
        float lg1 = __ldg(bo + lane);
        bool has2 = lane < (NOUT - 32);
        float lg2 = has2 ? __ldg(bo + 32 + lane) : 0.f;
#pragma unroll
        for (int c = 0; c < CC; c++) {
            float xc = xv[c];
            lg1 += xc * __ldg(Wo + c * NOUT + lane);
            if (has2) lg2 += xc * __ldg(Wo + c * NOUT + 32 + lane);
        }
        float m = has2 ? fmaxf(lg1, lg2) : lg1;
#pragma unroll
        for (int o = 16; o > 0; o >>= 1) m = fmaxf(m, __shfl_xor_sync(0xffffffffu, m, o));
        float se = __expf(lg1 - m) + (has2 ? __expf(lg2 - m) : 0.f);
#pragma unroll
        for (int o = 16; o > 0; o >>= 1) se += __shfl_xor_sync(0xffffffffu, se, o);
        float lse = m + __logf(se);
        fout[(size_t)dst * NOUT + lane] = lg1 - lse;
        if (has2) fout[(size_t)dst * NOUT + 32 + lane] = lg2 - lse;
    }
}

// ---------------- launch ----------------
extern "C" void kernel_launch(void* const* d_in, const int* in_sizes, int n_in,
                              void* d_out, int out_size) {
    const float* x   = (const float*)d_in[0];
    const int*   ei  = (const int*)d_in[1];
    const float* W1  = (const float*)d_in[2];
    const float* as1 = (const float*)d_in[3];
    const float* ad1 = (const float*)d_in[4];
    const float* b1  = (const float*)d_in[5];
    const float* W2  = (const float*)d_in[6];
    const float* as2 = (const float*)d_in[7];
    const float* ad2 = (const float*)d_in[8];
    const float* b2  = (const float*)d_in[9];
    const float* Wo  = (const float*)d_in[10];
    const float* bo  = (const float*)d_in[11];
    float* out = (float*)d_out;

    unsigned char* hbuf;
    float *act1, *pasrc, *padst;
    cudaGetSymbolAddress((void**)&hbuf, g_h);
    cudaGetSymbolAddress((void**)&act1, g_act1);
    cudaGetSymbolAddress((void**)&pasrc, g_asrc);
    cudaGetSymbolAddress((void**)&padst, g_adst);

    // one-time host resources for the parallel graph branch (no device memory)
    static cudaStream_t s_side = nullptr;
    static cudaEvent_t e_fork = nullptr, e_join = nullptr;
    if (s_side == nullptr) {
        cudaStreamCreateWithFlags(&s_side, cudaStreamNonBlocking);
        cudaEventCreateWithFlags(&e_fork, cudaEventDisableTiming);
        cudaEventCreateWithFlags(&e_join, cudaEventDisableTiming);
    }

    // ---- fork: GEMM1 (w/ fused alpha1) parallel to CSR build ----
    cudaEventRecord(e_fork, 0);
    cudaStreamWaitEvent(s_side, e_fork, 0);

    dim3 gg(HC / GBN, (NN + GBM - 1) / GBM);
    gemm_bf16<<<gg, 256, 0, s_side>>>(x, W1, hbuf, as1, ad1, NN, HC, FIN);
    cudaEventRecord(e_join, s_side);

    // ---- CSR build on the main stream ----
    zero_kernel<<<NB, 256>>>();
    count_kernel<<<(EE + 255) / 256, 256>>>(ei);
    degsum_kernel<<<NB, 256>>>();
    scanb_kernel<<<1, 256>>>();
    scanc_kernel<<<NB, 256>>>();
    fill_kernel<<<(EE + 255) / 256, 256>>>(ei);

    // ---- join: aggregate1 needs both branches ----
    cudaStreamWaitEvent(0, e_join, 0);
    aggregate_kernel<<<(NN * 32 + 255) / 256, 256>>>(hbuf, pasrc, padst, b1, act1,
                                                     nullptr, nullptr, nullptr);

    // ---- layer 2: GEMM2 (w/ fused alpha2), then aggregate2 (w/ fused final) ----
    gemm_bf16<<<gg, 256>>>(act1, W2, hbuf, as2, ad2, NN, HC, CC);
    aggregate_kernel<<<(NN * 32 + 255) / 256, 256>>>(hbuf, pasrc, padst, b2, nullptr,
                                                     Wo, bo, out);
}

// round 10
// speedup vs baseline: 1.3118x; 1.0101x over previous
#include <cuda_runtime.h>
#include <cuda_bf16.h>
#include <cuda_fp8.h>
#include <mma.h>

using namespace nvcuda;

#define NN   50000
#define EE   800000
#define FIN  256
#define HH   8
#define CC   32
#define HC   256   // HH*CC
#define NOUT 40
#define NEG_SLOPE 0.2f
#define NB   ((NN + 255) / 256)

// ---------------- device scratch ----------------
__device__ unsigned char g_h[(size_t)NN * HC];   // 12.8 MB : projected features (fp8 e4m3)
__device__ float g_act1[(size_t)NN * CC];
__device__ float g_asrc[NN * HH];
__device__ float g_adst[NN * HH];
__device__ int   g_deg[NN];
__device__ int   g_rowptr[NN + 1];
__device__ int   g_rank[EE];      // per-edge rank within its dst bucket
__device__ int   g_csr[EE];
__device__ int   g_bsum[NB];

// fp8x2 -> float2 helper
__device__ __forceinline__ float2 fp8x2_to_float2(unsigned short v) {
    __half2_raw hr = __nv_cvt_fp8x2_to_halfraw2((__nv_fp8x2_storage_t)v, __NV_E4M3);
    return __half22float2(*(__half2*)&hr);
}

// ---------------- CSR build ----------------
// count also records each edge's rank (return of atomicAdd) -> fill needs no atomics.
__global__ void count_kernel(const int* __restrict__ ei) {
    int e = blockIdx.x * blockDim.x + threadIdx.x;
    if (e < EE) g_rank[e] = atomicAdd(&g_deg[ei[EE + e]], 1);
}

__global__ void degsum_kernel() {
    __shared__ int sm[256];
    int i = blockIdx.x * 256 + threadIdx.x;
    int v = (i < NN) ? g_deg[i] : 0;
    sm[threadIdx.x] = v;
    __syncthreads();
    for (int o = 128; o > 0; o >>= 1) {
        if (threadIdx.x < o) sm[threadIdx.x] += sm[threadIdx.x + o];
        __syncthreads();
    }
    if (threadIdx.x == 0) g_bsum[blockIdx.x] = sm[0];
}

// fused: every block redundantly scans the 196 partials for its offset, then local scan
__global__ void scan_kernel() {
    __shared__ int sb[256];
    __shared__ int sm[256];
    int b = blockIdx.x, t = threadIdx.x;

    int v0 = (t < NB) ? g_bsum[t] : 0;
    sb[t] = v0;
    __syncthreads();
    for (int o = 1; o < 256; o <<= 1) {
        int u = (t >= o) ? sb[t - o] : 0;
        __syncthreads();
        sb[t] += u;
        __syncthreads();
    }
    int boff = (b == 0) ? 0 : sb[b - 1];   // exclusive prefix of block sums

    int i = b * 256 + t;
    int v = (i < NN) ? g_deg[i] : 0;
    sm[t] = v;
    __syncthreads();
    for (int o = 1; o < 256; o <<= 1) {
        int u = (t >= o) ? sm[t - o] : 0;
        __syncthreads();
        sm[t] += u;
        __syncthreads();
    }
    int excl = boff + sm[t] - v;
    if (i < NN) g_rowptr[i] = excl;
    if (i == NN - 1) g_rowptr[NN] = excl + v;
}

// atomic-free fill using precomputed rank
__global__ void fill_kernel(const int* __restrict__ ei) {
    int e = blockIdx.x * blockDim.x + threadIdx.x;
    if (e < EE) {
        int src = ei[e];
        int dst = ei[EE + e];
        g_csr[g_rowptr[dst] + g_rank[e]] = src;
    }
}

// ---------------- bf16 tensor-core GEMM, fp8 output, fused alpha epilogue ----------------
#define GBM 128
#define GBN 128
#define GBK 32
__global__ __launch_bounds__(256) void gemm_bf16(const float* __restrict__ A,
                                                 const float* __restrict__ B,
                                                 unsigned char* __restrict__ Cmat,
                                                 const float* __restrict__ a_src,
                                                 const float* __restrict__ a_dst,
                                                 int M, int Nc, int K) {
    __shared__ __nv_bfloat16 As[GBM][GBK + 8];
    __shared__ __nv_bfloat16 Bs[GBK][GBN + 8];
    __shared__ float stage[8][16 * 20];

    int tid = threadIdx.x;
    int wid = tid >> 5;
    int lane = tid & 31;
    int wm = wid >> 1;
    int wn = wid & 1;
    int bm = blockIdx.y * GBM;
    int bn = blockIdx.x * GBN;

    wmma::fragment<wmma::accumulator, 16, 16, 16, float> acc[2][4];
#pragma unroll
    for (int i = 0; i < 2; i++)
#pragma unroll
        for (int j = 0; j < 4; j++)
            wmma::fill_fragment(acc[i][j], 0.0f);

    int arow = tid >> 1;
    int acol = (tid & 1) * 16;
    int brow = tid >> 3;
    int bcol = (tid & 7) * 16;

    for (int k0 = 0; k0 < K; k0 += GBK) {
        {
            float4 v[4];
            if (bm + arow < M) {
                const float4* ap = (const float4*)(A + (size_t)(bm + arow) * K + k0 + acol);
#pragma unroll
                for (int t = 0; t < 4; t++) v[t] = ap[t];
            } else {
#pragma unroll
                for (int t = 0; t < 4; t++) v[t] = make_float4(0.f, 0.f, 0.f, 0.f);
            }
            __nv_bfloat16* dstp = &As[arow][acol];
#pragma unroll
            for (int t = 0; t < 4; t++) {
                dstp[4 * t + 0] = __float2bfloat16_rn(v[t].x);
                dstp[4 * t + 1] = __float2bfloat16_rn(v[t].y);
                dstp[4 * t + 2] = __float2bfloat16_rn(v[t].z);
                dstp[4 * t + 3] = __float2bfloat16_rn(v[t].w);
            }
        }
        {
            const float4* bp = (const float4*)(B + (size_t)(k0 + brow) * Nc + bn + bcol);
            __nv_bfloat16* dstp = &Bs[brow][bcol];
#pragma unroll
            for (int t = 0; t < 4; t++) {
                float4 v = bp[t];
                dstp[4 * t + 0] = __float2bfloat16_rn(v.x);
                dstp[4 * t + 1] = __float2bfloat16_rn(v.y);
                dstp[4 * t + 2] = __float2bfloat16_rn(v.z);
                dstp[4 * t + 3] = __float2bfloat16_rn(v.w);
            }
        }
        __syncthreads();
#pragma unroll
        for (int ks = 0; ks < GBK; ks += 16) {
            wmma::fragment<wmma::matrix_a, 16, 16, 16, __nv_bfloat16, wmma::row_major> af[2];
#pragma unroll
            for (int i = 0; i < 2; i++)
                wmma::load_matrix_sync(af[i], &As[wm * 32 + i * 16][ks], GBK + 8);
            wmma::fragment<wmma::matrix_b, 16, 16, 16, __nv_bfloat16, wmma::row_major> bf[4];
#pragma unroll
            for (int j = 0; j < 4; j++)
                wmma::load_matrix_sync(bf[j], &Bs[ks][wn * 64 + j * 16], GBN + 8);
#pragma unroll
            for (int i = 0; i < 2; i++)
#pragma unroll
                for (int j = 0; j < 4; j++)
                    wmma::mma_sync(acc[i][j], af[i], bf[j], acc[i][j]);
        }
        __syncthreads();
    }

    float* st = &stage[wid][0];
    int lr = lane >> 1;
    int lc = (lane & 1) * 8;
    int hb = (bn >> 5) + wn * 2;   // base head index for this warp (2 heads)
#pragma unroll
    for (int i = 0; i < 2; i++) {
        float al_s[2] = {0.f, 0.f};
        float al_d[2] = {0.f, 0.f};
        int row = bm + wm * 32 + i * 16 + lr;
#pragma unroll
        for (int j = 0; j < 4; j++) {
            wmma::store_matrix_sync(st, acc[i][j], 20, wmma::mem_row_major);
            __syncwarp();
            if (row < M) {
                int h = j >> 1;
                int colbase = (j & 1) * 16 + lc;   // column within head (0..31)
                const float* asp = a_src + (hb + h) * CC + colbase;
                const float* adp = a_dst + (hb + h) * CC + colbase;
                unsigned char tmp[8];
#pragma unroll
                for (int t = 0; t < 8; t++) {
                    float v = st[lr * 20 + lc + t];
                    tmp[t] = __nv_cvt_float_to_fp8(v, __NV_SATFINITE, __NV_E4M3);
                    al_s[h] += v * __ldg(asp + t);
                    al_d[h] += v * __ldg(adp + t);
                }
                int col = bn + wn * 64 + j * 16 + lc;
                *(uint2*)(Cmat + (size_t)row * Nc + col) = *(uint2*)tmp;
            }
            __syncwarp();
        }
#pragma unroll
        for (int h = 0; h < 2; h++) {
            float vs = al_s[h] + __shfl_xor_sync(0xffffffffu, al_s[h], 1);
            float vd = al_d[h] + __shfl_xor_sync(0xffffffffu, al_d[h], 1);
            if (row < M && (lane & 1) == 0) {
                g_asrc[row * HH + hb + h] = vs;
                g_adst[row * HH + hb + h] = vd;
            }
        }
    }
}

__device__ __forceinline__ float lrelu(float e) { return e > 0.f ? e : NEG_SLOPE * e; }

// fp8x8 (uint2) -> accumulate 8 channels
__device__ __forceinline__ void accum8(float* acc, float ex, const uint2& raw) {
    const unsigned short* p = (const unsigned short*)&raw;
#pragma unroll
    for (int t = 0; t < 4; t++) {
        float2 v = fp8x2_to_float2(p[t]);
        acc[2 * t]     += ex * v.x;
        acc[2 * t + 1] += ex * v.y;
    }
}

// ---------------- single-pass gather aggregation, dual-mode tail ----------------
__global__ __launch_bounds__(256) void aggregate_kernel(const unsigned char* __restrict__ hbuf,
                                                        const float* __restrict__ asrc,
                                                        const float* __restrict__ adst,
                                                        const float* __restrict__ bias,
                                                        float* __restrict__ outbuf,
                                                        const float* __restrict__ Wo,
                                                        const float* __restrict__ bo,
                                                        float* __restrict__ fout) {
    __shared__ float sx[8][32];

    int w = (blockIdx.x * blockDim.x + threadIdx.x) >> 5;
    int wib = threadIdx.x >> 5;
    int lane = threadIdx.x & 31;
    if (w >= NN) return;
    int dst = w;
    int beg = g_rowptr[dst], end = g_rowptr[dst + 1];
    int hd = lane >> 2;
    int cb = (lane & 3) * 8;
    float adst_h = adst[dst * HH + hd];

    float ex_self = __expf(lrelu(asrc[dst * HH + hd] + adst_h));
    float s = ex_self;
    float acc[8] = {0.f, 0.f, 0.f, 0.f, 0.f, 0.f, 0.f, 0.f};
    {
        uint2 raw = *(const uint2*)(hbuf + (size_t)dst * HC + hd * CC + cb);
        accum8(acc, ex_self, raw);
    }

    if (beg < end) {
        int src0 = g_csr[beg];
        float a0 = asrc[src0 * HH + hd];
        uint2 r0 = *(const uint2*)(hbuf + (size_t)src0 * HC + hd * CC + cb);
        for (int i = beg + 1; i < end; ++i) {
            int src1 = g_csr[i];
            float a1 = asrc[src1 * HH + hd];
            uint2 r1 = *(const uint2*)(hbuf + (size_t)src1 * HC + hd * CC + cb);
            float ex = __expf(lrelu(a0 + adst_h));
            s += ex;
            accum8(acc, ex, r0);
            a0 = a1; r0 = r1;
        }
        float ex = __expf(lrelu(a0 + adst_h));
        s += ex;
        accum8(acc, ex, r0);
    }

    float inv = 1.f / s;
#pragma unroll
    for (int j = 0; j < 8; j++) acc[j] *= inv;

#pragma unroll
    for (int j = 0; j < 8; j++) {
        float v = acc[j];
        v += __shfl_xor_sync(0xffffffffu, v, 4);
        v += __shfl_xor_sync(0xffffffffu, v, 8);
        v += __shfl_xor_sync(0xffffffffu, v, 16);
        acc[j] = v * 0.125f;
    }

    if (fout == nullptr) {
        if (lane < 4) {
            float o[8];
#pragma unroll
            for (int j = 0; j < 8; j++) {
                float v = acc[j] + bias[cb + j];
                o[j] = v > 0.f ? v : (__expf(v) - 1.f);
            }
            float4* op = (float4*)(outbuf + (size_t)dst * CC + cb);
            op[0] = make_float4(o[0], o[1], o[2], o[3]);
            op[1] = make_float4(o[4], o[5], o[6], o[7]);
        }
    } else {
        if (lane < 4) {
#pragma unroll
            for (int j = 0; j < 8; j++) {
                float v = acc[j] + bias[cb + j];
                sx[wib][cb + j] = v > 0.f ? v : (__expf(v) - 1.f);
            }
        }
        __syncwarp();
        const float* xv = sx[wib];
        float lg1 = __ldg(bo + lane);
        bool has2 = lane < (NOUT - 32);
        float lg2 = has2 ? __ldg(bo + 32 + lane) : 0.f;
#pragma unroll
        for (int c = 0; c < CC; c++) {
            float xc = xv[c];
            lg1 += xc * __ldg(Wo + c * NOUT + lane);
            if (has2) lg2 += xc * __ldg(Wo + c * NOUT + 32 + lane);
        }
        float m = has2 ? fmaxf(lg1, lg2) : lg1;
#pragma unroll
        for (int o = 16; o > 0; o >>= 1) m = fmaxf(m, __shfl_xor_sync(0xffffffffu, m, o));
        float se = __expf(lg1 - m) + (has2 ? __expf(lg2 - m) : 0.f);
#pragma unroll
        for (int o = 16; o > 0; o >>= 1) se += __shfl_xor_sync(0xffffffffu, se, o);
        float lse = m + __logf(se);
        fout[(size_t)dst * NOUT + lane] = lg1 - lse;
        if (has2) fout[(size_t)dst * NOUT + 32 + lane] = lg2 - lse;
    }
}

// ---------------- launch ----------------
extern "C" void kernel_launch(void* const* d_in, const int* in_sizes, int n_in,
                              void* d_out, int out_size) {
    const float* x   = (const float*)d_in[0];
    const int*   ei  = (const int*)d_in[1];
    const float* W1  = (const float*)d_in[2];
    const float* as1 = (const float*)d_in[3];
    const float* ad1 = (const float*)d_in[4];
    const float* b1  = (const float*)d_in[5];
    const float* W2  = (const float*)d_in[6];
    const float* as2 = (const float*)d_in[7];
    const float* ad2 = (const float*)d_in[8];
    const float* b2  = (const float*)d_in[9];
    const float* Wo  = (const float*)d_in[10];
    const float* bo  = (const float*)d_in[11];
    float* out = (float*)d_out;

    unsigned char* hbuf;
    float *act1, *pasrc, *padst;
    int* pdeg;
    cudaGetSymbolAddress((void**)&hbuf, g_h);
    cudaGetSymbolAddress((void**)&act1, g_act1);
    cudaGetSymbolAddress((void**)&pasrc, g_asrc);
    cudaGetSymbolAddress((void**)&padst, g_adst);
    cudaGetSymbolAddress((void**)&pdeg, g_deg);

    // one-time host resources for the parallel graph branch (no device memory)
    static cudaStream_t s_side = nullptr;
    static cudaEvent_t e_fork = nullptr, e_join = nullptr;
    if (s_side == nullptr) {
        cudaStreamCreateWithFlags(&s_side, cudaStreamNonBlocking);
        cudaEventCreateWithFlags(&e_fork, cudaEventDisableTiming);
        cudaEventCreateWithFlags(&e_join, cudaEventDisableTiming);
    }

    // ---- fork: GEMM1 (w/ fused alpha1) parallel to CSR build ----
    cudaEventRecord(e_fork, 0);
    cudaStreamWaitEvent(s_side, e_fork, 0);

    dim3 gg(HC / GBN, (NN + GBM - 1) / GBM);
    gemm_bf16<<<gg, 256, 0, s_side>>>(x, W1, hbuf, as1, ad1, NN, HC, FIN);
    cudaEventRecord(e_join, s_side);

    // ---- CSR build on the main stream (4 kernels + memset) ----
    cudaMemsetAsync(pdeg, 0, NN * sizeof(int), 0);
    count_kernel<<<(EE + 255) / 256, 256>>>(ei);
    degsum_kernel<<<NB, 256>>>();
    scan_kernel<<<NB, 256>>>();
    fill_kernel<<<(EE + 255) / 256, 256>>>(ei);

    // ---- join: aggregate1 needs both branches ----
    cudaStreamWaitEvent(0, e_join, 0);
    aggregate_kernel<<<(NN * 32 + 255) / 256, 256>>>(hbuf, pasrc, padst, b1, act1,
                                                     nullptr, nullptr, nullptr);

    // ---- layer 2: GEMM2 (w/ fused alpha2), then aggregate2 (w/ fused final) ----
    gemm_bf16<<<gg, 256>>>(act1, W2, hbuf, as2, ad2, NN, HC, CC);
    aggregate_kernel<<<(NN * 32 + 255) / 256, 256>>>(hbuf, pasrc, padst, b2, nullptr,
                                                     Wo, bo, out);
}